// round 15
// baseline (speedup 1.0000x reference)
#include <cuda_runtime.h>
#include <cuda_fp16.h>
#include <stdint.h>
#include <math.h>

// ---------------- problem dims ----------------
#define B_   4096
#define H_   512
#define LH_  1024
#define E_   2048
#define NG_  4096   // 4*LH

// ---------------- GEMM tiling ----------------
#define BM 128
#define BN 128
#define BK 32
#define SROW 40                    // halves per smem row (80 B): conflict-free ldmatrix
// warp-private staging: per warp per stage: A 64xBK + B 64xBK
#define WOP_B   (64 * SROW * 2)    // bytes per operand slice = 5120
#define WSTAGE_B (2 * WOP_B)       // per warp per stage (A+B) = 10240
#define WREGION_B (2 * WSTAGE_B)   // per warp, 2 stages = 20480
#define SMEM_BYTES (4 * WREGION_B) // 81920 -> 2 CTAs/SM (163840 <= 228KB)

// ---------------- scratch (static device memory) ----------------
__device__ __half g_xh  [(size_t)B_ * E_];     // embedded input, fp16
__device__ __half g_ench[(size_t)B_ * 2 * H_]; // encoder state, fp16
__device__ float  g_hc0 [(size_t)B_ * LH_];    // bridge output dup, fp32 (c_prev)
__device__ __half g_hc0h[(size_t)B_ * LH_];    // bridge output dup, fp16 (GEMM operand)
__device__ float  g_gates[(size_t)B_ * NG_];   // gate pre-activations, fp32
__device__ __half g_h1h [(size_t)B_ * LH_];    // layer-1 hidden, fp16
__device__ __half g_wh  [(size_t)20 * 1024 * 1024]; // fp16 weights: ih1(8M) hh1(4M) ih2(4M) hh2(4M)
__device__ __half g_bwh [(size_t)H_ * 2 * H_]; // fp16 bridge_W
__device__ float  g_b1[NG_];                   // b_ih1 + b_hh1
__device__ float  g_b2[NG_];                   // b_ih2 + b_hh2

// ---------------- helpers ----------------
__device__ __forceinline__ uint32_t smem_u32(const void* p)
{
    uint32_t a;
    asm("{ .reg .u64 t; cvta.to.shared.u64 t, %1; cvt.u32.u64 %0, t; }" : "=r"(a) : "l"(p));
    return a;
}

__device__ __forceinline__ void cp16(uint32_t sa, const void* g)
{
    asm volatile("cp.async.cg.shared.global [%0], [%1], 16;" :: "r"(sa), "l"(g));
}

__device__ __forceinline__ void ldsm4(uint32_t* r, uint32_t addr)
{
    asm volatile("ldmatrix.sync.aligned.m8n8.x4.shared.b16 {%0,%1,%2,%3}, [%4];"
                 : "=r"(r[0]), "=r"(r[1]), "=r"(r[2]), "=r"(r[3]) : "r"(addr));
}

__device__ __forceinline__ uint2 pack_h4(float4 v)
{
    __half2 lo = __floats2half2_rn(v.x, v.y);
    __half2 hi = __floats2half2_rn(v.z, v.w);
    uint2 o;
    o.x = *(const uint32_t*)&lo;
    o.y = *(const uint32_t*)&hi;
    return o;
}

__device__ __forceinline__ void f2h_block(const float4* __restrict__ src,
                                          uint2* __restrict__ dst, int blk)
{
    int base = blk * 1024 + threadIdx.x;
    float4 v0 = src[base];
    float4 v1 = src[base + 256];
    float4 v2 = src[base + 512];
    float4 v3 = src[base + 768];
    dst[base]       = pack_h4(v0);
    dst[base + 256] = pack_h4(v1);
    dst[base + 512] = pack_h4(v2);
    dst[base + 768] = pack_h4(v3);
}

// ---------------- single merged prep kernel ----------------
__global__ void prep_all(const float4* __restrict__ w_ih1, const float4* __restrict__ w_hh1,
                         const float4* __restrict__ w_ih2, const float4* __restrict__ w_hh2,
                         const float4* __restrict__ bw,    const float4* __restrict__ enc,
                         uint2* __restrict__ w_ih1h, uint2* __restrict__ w_hh1h,
                         uint2* __restrict__ w_ih2h, uint2* __restrict__ w_hh2h,
                         uint2* __restrict__ bwh,    uint2* __restrict__ ench,
                         const float* __restrict__ bi1a, const float* __restrict__ bi1b,
                         float* __restrict__ b1,
                         const float* __restrict__ bi2a, const float* __restrict__ bi2b,
                         float* __restrict__ b2)
{
    int b = blockIdx.x;
    if (b < 2048)       f2h_block(w_ih1, w_ih1h, b);
    else if (b < 3072)  f2h_block(w_hh1, w_hh1h, b - 2048);
    else if (b < 4096)  f2h_block(w_ih2, w_ih2h, b - 3072);
    else if (b < 5120)  f2h_block(w_hh2, w_hh2h, b - 4096);
    else if (b < 5248)  f2h_block(bw,    bwh,    b - 5120);
    else if (b < 6272)  f2h_block(enc,   ench,   b - 5248);
    else if (b == 6272) {
        for (int i = threadIdx.x; i < NG_; i += 256) b1[i] = bi1a[i] + bi1b[i];
    } else {
        for (int i = threadIdx.x; i < NG_; i += 256) b2[i] = bi2a[i] + bi2b[i];
    }
}

__global__ void gather_kernel(const int* __restrict__ input,
                              const float4* __restrict__ emb,
                              uint2* __restrict__ xh)
{
    int idx = blockIdx.x * blockDim.x + threadIdx.x;   // over B * (E/4)
    int b = idx >> 9;            // E/4 = 512
    int j = idx & 511;
    int tok = input[b];
    xh[idx] = pack_h4(emb[(size_t)tok * 512 + j]);
}

// ---------------- barrier-free fp16 mma.sync GEMM ----------------
// 128 threads, 4 warps of 64x64. Each warp loads its OWN A/B slices into a
// private 2-stage smem region via per-thread cp.async groups -> NO __syncthreads
// in the mainloop; co-resident warps drift apart and keep the tensor pipe fed.
// C[M,N] = A1 @ W1^T + A2 @ W2^T + bias   (half operands K-major, fp32 accum)
// epi=0: C[row*N + col] = v  (gates)
// epi=1: bridge duplicate (N=512)
__global__ void __launch_bounds__(128, 2)
gemm_fp16_kernel(const __half* __restrict__ A1, const __half* __restrict__ W1, int K1,
                 const __half* __restrict__ A2, const __half* __restrict__ W2, int K2,
                 const float* __restrict__ bias,
                 float* __restrict__ C, __half* __restrict__ Ch, int N, int epi)
{
    extern __shared__ __half smem[];
    const int tid  = threadIdx.x;
    const int lane = tid & 31;
    const int warp = tid >> 5;
    const int wm = (warp & 1) * 64;
    const int wn = (warp >> 1) * 64;
    const int bm = blockIdx.y * BM;
    const int bn = blockIdx.x * BN;

    const uint32_t wbase = smem_u32(smem) + warp * WREGION_B;   // this warp's region

    float acc[4][8][4];
    #pragma unroll
    for (int mi = 0; mi < 4; ++mi)
        #pragma unroll
        for (int ni = 0; ni < 8; ++ni)
            #pragma unroll
            for (int r = 0; r < 4; ++r)
                acc[mi][ni][r] = 0.0f;

    const int nk = (K1 + K2) / BK;

    // warp-private tile load: A rows [bm+wm,+64), B rows [bn+wn,+64), BK cols
    auto load_tile = [&](int kt, int s) {
        int kk = kt * BK;
        const __half* As; const __half* Bs; int ld;
        if (kk < K1) { As = A1 + kk; Bs = W1 + kk; ld = K1; }
        else         { As = A2 + (kk - K1); Bs = W2 + (kk - K1); ld = K2; }
        uint32_t a_dst = wbase + s * WSTAGE_B;
        uint32_t b_dst = a_dst + WOP_B;
        #pragma unroll
        for (int it = 0; it < 8; ++it) {
            int idx = lane + it * 32;       // 0..255
            int row = idx >> 2;             // 0..63
            int c8  = (idx & 3) << 3;       // half offset 0,8,16,24
            uint32_t off = (uint32_t)(row * SROW + c8) * 2;
            cp16(a_dst + off, As + (size_t)(bm + wm + row) * ld + c8);
            cp16(b_dst + off, Bs + (size_t)(bn + wn + row) * ld + c8);
        }
        asm volatile("cp.async.commit_group;");
    };

    load_tile(0, 0);
    load_tile(1, 1);

    // per-lane ldmatrix base offsets within the warp-private slices (bytes)
    const uint32_t la = (uint32_t)((lane & 15) * SROW + ((lane >> 4) << 3)) * 2;
    const uint32_t lb = (uint32_t)(((lane & 7) + ((lane >> 4) << 3)) * SROW +
                                   (((lane >> 3) & 1) << 3)) * 2;

    for (int kt = 0; kt < nk; ++kt) {
        if (kt + 1 < nk) asm volatile("cp.async.wait_group 1;");
        else             asm volatile("cp.async.wait_group 0;");
        __syncwarp();

        const int s = kt & 1;
        const uint32_t sa = wbase + s * WSTAGE_B + la;
        const uint32_t sb = wbase + s * WSTAGE_B + WOP_B + lb;

        #pragma unroll
        for (int ks = 0; ks < 2; ++ks) {            // two k16 halves of BK=32
            uint32_t a[4][4], b[4][4];
            #pragma unroll
            for (int mi = 0; mi < 4; ++mi)
                ldsm4(a[mi], sa + ((mi * 16 * SROW + ks * 16) << 1));
            #pragma unroll
            for (int g = 0; g < 4; ++g)
                ldsm4(b[g], sb + ((g * 16 * SROW + ks * 16) << 1));
            #pragma unroll
            for (int mi = 0; mi < 4; ++mi)
                #pragma unroll
                for (int ni = 0; ni < 8; ++ni) {
                    float* d = acc[mi][ni];
                    uint32_t b0 = b[ni >> 1][(ni & 1) * 2];
                    uint32_t b1 = b[ni >> 1][(ni & 1) * 2 + 1];
                    asm volatile(
                        "mma.sync.aligned.m16n8k16.row.col.f32.f16.f16.f32 "
                        "{%0,%1,%2,%3}, {%4,%5,%6,%7}, {%8,%9}, {%0,%1,%2,%3};"
                        : "+f"(d[0]), "+f"(d[1]), "+f"(d[2]), "+f"(d[3])
                        : "r"(a[mi][0]), "r"(a[mi][1]), "r"(a[mi][2]), "r"(a[mi][3]),
                          "r"(b0), "r"(b1));
                }
        }

        // refill this stage for tile kt+2 (LDSMs above are complete: their
        // results were consumed by the in-order-issued MMAs)
        if (kt + 2 < nk) load_tile(kt + 2, s);
    }

    // epilogue (warp-local, no barrier needed)
    #pragma unroll
    for (int mi = 0; mi < 4; ++mi) {
        int r0 = bm + wm + mi * 16 + (lane >> 2);
        #pragma unroll
        for (int ni = 0; ni < 8; ++ni) {
            int c0 = bn + wn + ni * 8 + ((lane & 3) << 1);
            float bv0 = bias[c0], bv1 = bias[c0 + 1];
            float v00 = acc[mi][ni][0] + bv0;
            float v01 = acc[mi][ni][1] + bv1;
            float v10 = acc[mi][ni][2] + bv0;
            float v11 = acc[mi][ni][3] + bv1;
            if (epi == 0) {
                *(float2*)(C + (size_t)r0 * N + c0)       = make_float2(v00, v01);
                *(float2*)(C + (size_t)(r0 + 8) * N + c0) = make_float2(v10, v11);
            } else {
                size_t o0 = (size_t)r0 * LH_ + c0;
                size_t o1 = (size_t)(r0 + 8) * LH_ + c0;
                __half2 h0 = __floats2half2_rn(v00, v01);
                __half2 h1 = __floats2half2_rn(v10, v11);
                *(float2*)(C + o0)        = make_float2(v00, v01);
                *(float2*)(C + o0 + H_)   = make_float2(v00, v01);
                *(float2*)(C + o1)        = make_float2(v10, v11);
                *(float2*)(C + o1 + H_)   = make_float2(v10, v11);
                *(__half2*)(Ch + o0)      = h0;
                *(__half2*)(Ch + o0 + H_) = h0;
                *(__half2*)(Ch + o1)      = h1;
                *(__half2*)(Ch + o1 + H_) = h1;
            }
        }
    }
}

// ---------------- LSTM pointwise activation (float4) ----------------
__global__ void lstm_act_kernel(const float4* __restrict__ gates,
                                const float4* __restrict__ cprev,
                                float4* __restrict__ outF1,
                                float4* __restrict__ outF2,
                                __half2* __restrict__ outH)
{
    int idx = blockIdx.x * blockDim.x + threadIdx.x;   // over B*LH/4
    int b  = idx >> 8;           // LH/4 = 256
    int n4 = idx & 255;
    const float4* g = gates + (size_t)b * 1024 + n4;   // row = 1024 float4
    float4 gi = g[0];
    float4 gf = g[256];
    float4 gg = g[512];
    float4 go = g[768];
    float4 cp = cprev[idx];
    float4 h;
    {
        float i0 = 1.0f / (1.0f + expf(-gi.x));
        float f0 = 1.0f / (1.0f + expf(-gf.x));
        float o0 = 1.0f / (1.0f + expf(-go.x));
        float c0 = f0 * cp.x + i0 * tanhf(gg.x);
        h.x = o0 * tanhf(c0);
        float i1 = 1.0f / (1.0f + expf(-gi.y));
        float f1 = 1.0f / (1.0f + expf(-gf.y));
        float o1 = 1.0f / (1.0f + expf(-go.y));
        float c1 = f1 * cp.y + i1 * tanhf(gg.y);
        h.y = o1 * tanhf(c1);
        float i2 = 1.0f / (1.0f + expf(-gi.z));
        float f2 = 1.0f / (1.0f + expf(-gf.z));
        float o2 = 1.0f / (1.0f + expf(-go.z));
        float c2 = f2 * cp.z + i2 * tanhf(gg.z);
        h.z = o2 * tanhf(c2);
        float i3 = 1.0f / (1.0f + expf(-gi.w));
        float f3 = 1.0f / (1.0f + expf(-gf.w));
        float o3 = 1.0f / (1.0f + expf(-go.w));
        float c3 = f3 * cp.w + i3 * tanhf(gg.w);
        h.w = o3 * tanhf(c3);
    }
    outF1[idx] = h;
    if (outF2) outF2[idx] = h;
    if (outH) {
        outH[idx * 2]     = __floats2half2_rn(h.x, h.y);
        outH[idx * 2 + 1] = __floats2half2_rn(h.z, h.w);
    }
}

// ---------------- launch ----------------
extern "C" void kernel_launch(void* const* d_in, const int* in_sizes, int n_in,
                              void* d_out, int out_size)
{
    const int*   input    = (const int*)d_in[0];
    const float* enc      = (const float*)d_in[1];
    const float* bridge_W = (const float*)d_in[2];
    const float* bridge_b = (const float*)d_in[3];
    const float* emb      = (const float*)d_in[4];
    const float* w_ih1    = (const float*)d_in[5];
    const float* w_hh1    = (const float*)d_in[6];
    const float* b_ih1    = (const float*)d_in[7];
    const float* b_hh1    = (const float*)d_in[8];
    const float* w_ih2    = (const float*)d_in[9];
    const float* w_hh2    = (const float*)d_in[10];
    const float* b_ih2    = (const float*)d_in[11];
    const float* b_hh2    = (const float*)d_in[12];
    float* out = (float*)d_out;

    __half *xh, *ench, *hc0h, *h1h, *wh, *bwh;
    float *hc0, *gates, *b1, *b2;
    cudaGetSymbolAddress((void**)&xh,    g_xh);
    cudaGetSymbolAddress((void**)&ench,  g_ench);
    cudaGetSymbolAddress((void**)&hc0,   g_hc0);
    cudaGetSymbolAddress((void**)&hc0h,  g_hc0h);
    cudaGetSymbolAddress((void**)&gates, g_gates);
    cudaGetSymbolAddress((void**)&h1h,   g_h1h);
    cudaGetSymbolAddress((void**)&wh,    g_wh);
    cudaGetSymbolAddress((void**)&bwh,   g_bwh);
    cudaGetSymbolAddress((void**)&b1,    g_b1);
    cudaGetSymbolAddress((void**)&b2,    g_b2);

    __half* w_ih1h = wh;
    __half* w_hh1h = wh + (size_t)8  * 1024 * 1024;
    __half* w_ih2h = wh + (size_t)12 * 1024 * 1024;
    __half* w_hh2h = wh + (size_t)16 * 1024 * 1024;

    cudaFuncSetAttribute(gemm_fp16_kernel,
                         cudaFuncAttributeMaxDynamicSharedMemorySize, SMEM_BYTES);

    const size_t BLH = (size_t)B_ * LH_;

    // 1) all conversions + bias sums, one kernel
    prep_all<<<6274, 256>>>((const float4*)w_ih1, (const float4*)w_hh1,
                            (const float4*)w_ih2, (const float4*)w_hh2,
                            (const float4*)bridge_W, (const float4*)enc,
                            (uint2*)w_ih1h, (uint2*)w_hh1h,
                            (uint2*)w_ih2h, (uint2*)w_hh2h,
                            (uint2*)bwh, (uint2*)ench,
                            b_ih1, b_hh1, b1, b_ih2, b_hh2, b2);

    // 2) x = fp16(emb[input])
    gather_kernel<<<(B_ * (E_ / 4)) / 256, 256>>>(input, (const float4*)emb, (uint2*)xh);

    // 3) bridge: hc0 / hc0h = dup(enc @ bridge_W^T + b)   (M=B, N=512, K=1024)
    gemm_fp16_kernel<<<dim3(H_ / BN, B_ / BM), 128, SMEM_BYTES>>>(
        ench, bwh, 2 * H_, ench, bwh, 0,
        bridge_b, hc0, hc0h, H_, 1);

    // 4) gates1 = x @ w_ih1^T + hc0 @ w_hh1^T + b1
    gemm_fp16_kernel<<<dim3(NG_ / BN, B_ / BM), 128, SMEM_BYTES>>>(
        xh, w_ih1h, E_, hc0h, w_hh1h, LH_,
        b1, gates, nullptr, NG_, 0);

    // 5) h1: fp16 for GEMM, fp32 into hidden_state[0]
    lstm_act_kernel<<<(B_ * LH_ / 4) / 256, 256>>>(
        (const float4*)gates, (const float4*)hc0,
        (float4*)(out + BLH), nullptr, (__half2*)h1h);

    // 6) gates2 = h1 @ w_ih2^T + hc0 @ w_hh2^T + b2
    gemm_fp16_kernel<<<dim3(NG_ / BN, B_ / BM), 128, SMEM_BYTES>>>(
        h1h, w_ih2h, LH_, hc0h, w_hh2h, LH_,
        b2, gates, nullptr, NG_, 0);

    // 7) h2 -> output and hidden_state[1]
    lstm_act_kernel<<<(B_ * LH_ / 4) / 256, 256>>>(
        (const float4*)gates, (const float4*)hc0,
        (float4*)out, (float4*)(out + 2 * BLH), nullptr);
}

// round 16
// speedup vs baseline: 1.3634x; 1.3634x over previous
#include <cuda_runtime.h>
#include <cuda_fp16.h>
#include <stdint.h>
#include <math.h>

// ---------------- problem dims ----------------
#define B_   4096
#define H_   512
#define LH_  1024
#define E_   2048
#define NG_  4096   // 4*LH

// ---------------- GEMM tiling ----------------
#define BM 128
#define BN 128
#define BK 32
#define SROW 40                    // halves per smem row (80 B): conflict-free ldmatrix
#define STAGE_B (128 * SROW * 2)   // bytes per tile stage (A or B) = 10240
#define NSTAGE 3
#define SMEM_BYTES (2 * NSTAGE * STAGE_B)   // 61440

// ---------------- scratch (static device memory) ----------------
__device__ __half g_xh  [(size_t)B_ * E_];     // embedded input, fp16
__device__ __half g_ench[(size_t)B_ * 2 * H_]; // encoder state, fp16
__device__ float  g_h0f [(size_t)B_ * H_];     // bridge output, fp32 (c_prev half)
__device__ __half g_h0h [(size_t)B_ * H_];     // bridge output, fp16 (GEMM operand)
__device__ float  g_gates[(size_t)B_ * NG_];   // gate pre-activations, fp32
__device__ __half g_h1h [(size_t)B_ * LH_];    // layer-1 hidden, fp16
__device__ __half g_wh  [(size_t)20 * 1024 * 1024]; // fp16 weights: ih1(8M) ih2(4M) hh1f(2M) hh2f(2M)
__device__ __half g_bwh [(size_t)H_ * 2 * H_]; // fp16 bridge_W
__device__ float  g_b1[NG_];                   // b_ih1 + b_hh1
__device__ float  g_b2[NG_];                   // b_ih2 + b_hh2

// ---------------- helpers ----------------
__device__ __forceinline__ uint32_t smem_u32(const void* p)
{
    uint32_t a;
    asm("{ .reg .u64 t; cvta.to.shared.u64 t, %1; cvt.u32.u64 %0, t; }" : "=r"(a) : "l"(p));
    return a;
}

__device__ __forceinline__ void cp16(uint32_t sa, const void* g)
{
    asm volatile("cp.async.cg.shared.global [%0], [%1], 16;" :: "r"(sa), "l"(g));
}

__device__ __forceinline__ void ldsm4(uint32_t* r, uint32_t addr)
{
    asm volatile("ldmatrix.sync.aligned.m8n8.x4.shared.b16 {%0,%1,%2,%3}, [%4];"
                 : "=r"(r[0]), "=r"(r[1]), "=r"(r[2]), "=r"(r[3]) : "r"(addr));
}

__device__ __forceinline__ uint2 pack_h4(float4 v)
{
    __half2 lo = __floats2half2_rn(v.x, v.y);
    __half2 hi = __floats2half2_rn(v.z, v.w);
    uint2 o;
    o.x = *(const uint32_t*)&lo;
    o.y = *(const uint32_t*)&hi;
    return o;
}

__device__ __forceinline__ void f2h_block(const float4* __restrict__ src,
                                          uint2* __restrict__ dst, int blk)
{
    int base = blk * 1024 + threadIdx.x;
    float4 v0 = src[base];
    float4 v1 = src[base + 256];
    float4 v2 = src[base + 512];
    float4 v3 = src[base + 768];
    dst[base]       = pack_h4(v0);
    dst[base + 256] = pack_h4(v1);
    dst[base + 512] = pack_h4(v2);
    dst[base + 768] = pack_h4(v3);
}

// fold a [NG, 1024] w_hh into [NG, 512] fp16: out[n,k] = w[n,k] + w[n,k+512]
__device__ __forceinline__ void fold_block(const float4* __restrict__ src,
                                           uint2* __restrict__ dst, int blk)
{
    #pragma unroll
    for (int j = 0; j < 4; ++j) {
        int i = blk * 1024 + threadIdx.x + j * 256;  // output float4 index, 128 per row
        int row = i >> 7;
        int c4  = i & 127;
        float4 a = src[row * 256 + c4];
        float4 b = src[row * 256 + c4 + 128];
        float4 s;
        s.x = a.x + b.x; s.y = a.y + b.y; s.z = a.z + b.z; s.w = a.w + b.w;
        dst[i] = pack_h4(s);
    }
}

// ---------------- single merged prep kernel ----------------
// blocks: [0,2048) w_ih1 | [2048,3072) w_ih2 | [3072,3584) fold w_hh1 |
// [3584,4096) fold w_hh2 | [4096,4224) bridge_W | [4224,5248) enc | 5248 b1 | 5249 b2
__global__ void prep_all(const float4* __restrict__ w_ih1, const float4* __restrict__ w_hh1,
                         const float4* __restrict__ w_ih2, const float4* __restrict__ w_hh2,
                         const float4* __restrict__ bw,    const float4* __restrict__ enc,
                         uint2* __restrict__ w_ih1h, uint2* __restrict__ w_ih2h,
                         uint2* __restrict__ w_hh1f, uint2* __restrict__ w_hh2f,
                         uint2* __restrict__ bwh,    uint2* __restrict__ ench,
                         const float* __restrict__ bi1a, const float* __restrict__ bi1b,
                         float* __restrict__ b1,
                         const float* __restrict__ bi2a, const float* __restrict__ bi2b,
                         float* __restrict__ b2)
{
    int b = blockIdx.x;
    if (b < 2048)       f2h_block(w_ih1, w_ih1h, b);
    else if (b < 3072)  f2h_block(w_ih2, w_ih2h, b - 2048);
    else if (b < 3584)  fold_block(w_hh1, w_hh1f, b - 3072);
    else if (b < 4096)  fold_block(w_hh2, w_hh2f, b - 3584);
    else if (b < 4224)  f2h_block(bw,    bwh,    b - 4096);
    else if (b < 5248)  f2h_block(enc,   ench,   b - 4224);
    else if (b == 5248) {
        for (int i = threadIdx.x; i < NG_; i += 256) b1[i] = bi1a[i] + bi1b[i];
    } else {
        for (int i = threadIdx.x; i < NG_; i += 256) b2[i] = bi2a[i] + bi2b[i];
    }
}

__global__ void gather_kernel(const int* __restrict__ input,
                              const float4* __restrict__ emb,
                              uint2* __restrict__ xh)
{
    int idx = blockIdx.x * blockDim.x + threadIdx.x;   // over B * (E/4)
    int b = idx >> 9;            // E/4 = 512
    int j = idx & 511;
    int tok = input[b];
    xh[idx] = pack_h4(emb[(size_t)tok * 512 + j]);
}

// ---------------- fp16 mma.sync GEMM (R11 core) ----------------
// 128 threads, 4 warps of 64x64; 3-stage cp.async; ldmatrix per-ks.
// C[M,N] = A1 @ W1^T + A2 @ W2^T + bias   (half operands K-major, fp32 accum)
// epi=0: C[row*N + col] = v  (gates)
// epi=1: bridge (N=512): C fp32 [B,512] and Ch fp16 [B,512]
__global__ void __launch_bounds__(128, 2)
gemm_fp16_kernel(const __half* __restrict__ A1, const __half* __restrict__ W1, int K1,
                 const __half* __restrict__ A2, const __half* __restrict__ W2, int K2,
                 const float* __restrict__ bias,
                 float* __restrict__ C, __half* __restrict__ Ch, int N, int epi)
{
    extern __shared__ __half smem[];
    const uint32_t sbase = smem_u32(smem);
    const int tid  = threadIdx.x;
    const int lane = tid & 31;
    const int warp = tid >> 5;
    const int wm = (warp & 1) * 64;
    const int wn = (warp >> 1) * 64;
    const int bm = blockIdx.y * BM;
    const int bn = blockIdx.x * BN;

    float acc[4][8][4];
    #pragma unroll
    for (int mi = 0; mi < 4; ++mi)
        #pragma unroll
        for (int ni = 0; ni < 8; ++ni)
            #pragma unroll
            for (int r = 0; r < 4; ++r)
                acc[mi][ni][r] = 0.0f;

    const int nk = (K1 + K2) / BK;

    auto load_tile = [&](int kt, int s) {
        int kk = kt * BK;
        const __half* As; const __half* Bs; int ld;
        if (kk < K1) { As = A1 + kk; Bs = W1 + kk; ld = K1; }
        else         { As = A2 + (kk - K1); Bs = W2 + (kk - K1); ld = K2; }
        uint32_t a_dst = sbase + s * STAGE_B;
        uint32_t b_dst = sbase + NSTAGE * STAGE_B + s * STAGE_B;
        #pragma unroll
        for (int it = 0; it < 4; ++it) {
            int idx = tid + it * 128;       // 0..511
            int row = idx >> 2;             // 0..127
            int c8  = (idx & 3) << 3;       // half offset 0,8,16,24
            cp16(a_dst + (row * SROW + c8) * 2, As + (size_t)(bm + row) * ld + c8);
            cp16(b_dst + (row * SROW + c8) * 2, Bs + (size_t)(bn + row) * ld + c8);
        }
        asm volatile("cp.async.commit_group;");
    };

    load_tile(0, 0);
    load_tile(1, 1);

    // per-lane ldmatrix base addresses (bytes)
    const uint32_t base_a = sbase +
        (((wm + (lane & 15)) * SROW + ((lane >> 4) << 3)) << 1);
    const uint32_t base_b = sbase + NSTAGE * STAGE_B +
        (((wn + (lane & 7) + ((lane >> 4) << 3)) * SROW + (((lane >> 3) & 1) << 3)) << 1);

    for (int kt = 0; kt < nk; ++kt) {
        if (kt + 1 < nk) asm volatile("cp.async.wait_group 1;");
        else             asm volatile("cp.async.wait_group 0;");
        __syncthreads();
        if (kt + 2 < nk) load_tile(kt + 2, (kt + 2) % NSTAGE);

        const int s = kt % NSTAGE;
        const uint32_t sa = base_a + s * STAGE_B;
        const uint32_t sb = base_b + s * STAGE_B;

        #pragma unroll
        for (int ks = 0; ks < 2; ++ks) {            // two k16 halves of BK=32
            uint32_t a[4][4], b[4][4];
            #pragma unroll
            for (int mi = 0; mi < 4; ++mi)
                ldsm4(a[mi], sa + ((mi * 16 * SROW + ks * 16) << 1));
            #pragma unroll
            for (int g = 0; g < 4; ++g)
                ldsm4(b[g], sb + ((g * 16 * SROW + ks * 16) << 1));
            #pragma unroll
            for (int mi = 0; mi < 4; ++mi)
                #pragma unroll
                for (int ni = 0; ni < 8; ++ni) {
                    float* d = acc[mi][ni];
                    uint32_t b0 = b[ni >> 1][(ni & 1) * 2];
                    uint32_t b1 = b[ni >> 1][(ni & 1) * 2 + 1];
                    asm volatile(
                        "mma.sync.aligned.m16n8k16.row.col.f32.f16.f16.f32 "
                        "{%0,%1,%2,%3}, {%4,%5,%6,%7}, {%8,%9}, {%0,%1,%2,%3};"
                        : "+f"(d[0]), "+f"(d[1]), "+f"(d[2]), "+f"(d[3])
                        : "r"(a[mi][0]), "r"(a[mi][1]), "r"(a[mi][2]), "r"(a[mi][3]),
                          "r"(b0), "r"(b1));
                }
        }
    }

    // epilogue
    #pragma unroll
    for (int mi = 0; mi < 4; ++mi) {
        int r0 = bm + wm + mi * 16 + (lane >> 2);
        #pragma unroll
        for (int ni = 0; ni < 8; ++ni) {
            int c0 = bn + wn + ni * 8 + ((lane & 3) << 1);
            float bv0 = bias[c0], bv1 = bias[c0 + 1];
            float v00 = acc[mi][ni][0] + bv0;
            float v01 = acc[mi][ni][1] + bv1;
            float v10 = acc[mi][ni][2] + bv0;
            float v11 = acc[mi][ni][3] + bv1;
            if (epi == 0) {
                *(float2*)(C + (size_t)r0 * N + c0)       = make_float2(v00, v01);
                *(float2*)(C + (size_t)(r0 + 8) * N + c0) = make_float2(v10, v11);
            } else {
                size_t o0 = (size_t)r0 * H_ + c0;
                size_t o1 = (size_t)(r0 + 8) * H_ + c0;
                *(float2*)(C + o0)   = make_float2(v00, v01);
                *(float2*)(C + o1)   = make_float2(v10, v11);
                *(__half2*)(Ch + o0) = __floats2half2_rn(v00, v01);
                *(__half2*)(Ch + o1) = __floats2half2_rn(v10, v11);
            }
        }
    }
}

// ---------------- LSTM pointwise activation (float4) ----------------
// gates [B, 4LH] blocks i,f,g,o; cprev = h0f [B, 512] fp32 (c_prev = dup(h0)).
__global__ void lstm_act_kernel(const float4* __restrict__ gates,
                                const float4* __restrict__ cprev,
                                float4* __restrict__ outF1,
                                float4* __restrict__ outF2,
                                __half2* __restrict__ outH)
{
    int idx = blockIdx.x * blockDim.x + threadIdx.x;   // over B*LH/4
    int b  = idx >> 8;           // LH/4 = 256
    int n4 = idx & 255;
    const float4* g = gates + (size_t)b * 1024 + n4;   // row = 1024 float4
    float4 gi = g[0];
    float4 gf = g[256];
    float4 gg = g[512];
    float4 go = g[768];
    float4 cp = cprev[b * 128 + (n4 & 127)];           // dup(h0): index mod 512
    float4 h;
    {
        float i0 = 1.0f / (1.0f + expf(-gi.x));
        float f0 = 1.0f / (1.0f + expf(-gf.x));
        float o0 = 1.0f / (1.0f + expf(-go.x));
        float c0 = f0 * cp.x + i0 * tanhf(gg.x);
        h.x = o0 * tanhf(c0);
        float i1 = 1.0f / (1.0f + expf(-gi.y));
        float f1 = 1.0f / (1.0f + expf(-gf.y));
        float o1 = 1.0f / (1.0f + expf(-go.y));
        float c1 = f1 * cp.y + i1 * tanhf(gg.y);
        h.y = o1 * tanhf(c1);
        float i2 = 1.0f / (1.0f + expf(-gi.z));
        float f2 = 1.0f / (1.0f + expf(-gf.z));
        float o2 = 1.0f / (1.0f + expf(-go.z));
        float c2 = f2 * cp.z + i2 * tanhf(gg.z);
        h.z = o2 * tanhf(c2);
        float i3 = 1.0f / (1.0f + expf(-gi.w));
        float f3 = 1.0f / (1.0f + expf(-gf.w));
        float o3 = 1.0f / (1.0f + expf(-go.w));
        float c3 = f3 * cp.w + i3 * tanhf(gg.w);
        h.w = o3 * tanhf(c3);
    }
    outF1[idx] = h;
    if (outF2) outF2[idx] = h;
    if (outH) {
        outH[idx * 2]     = __floats2half2_rn(h.x, h.y);
        outH[idx * 2 + 1] = __floats2half2_rn(h.z, h.w);
    }
}

// ---------------- launch ----------------
extern "C" void kernel_launch(void* const* d_in, const int* in_sizes, int n_in,
                              void* d_out, int out_size)
{
    const int*   input    = (const int*)d_in[0];
    const float* enc      = (const float*)d_in[1];
    const float* bridge_W = (const float*)d_in[2];
    const float* bridge_b = (const float*)d_in[3];
    const float* emb      = (const float*)d_in[4];
    const float* w_ih1    = (const float*)d_in[5];
    const float* w_hh1    = (const float*)d_in[6];
    const float* b_ih1    = (const float*)d_in[7];
    const float* b_hh1    = (const float*)d_in[8];
    const float* w_ih2    = (const float*)d_in[9];
    const float* w_hh2    = (const float*)d_in[10];
    const float* b_ih2    = (const float*)d_in[11];
    const float* b_hh2    = (const float*)d_in[12];
    float* out = (float*)d_out;

    __half *xh, *ench, *h0h, *h1h, *wh, *bwh;
    float *h0f, *gates, *b1, *b2;
    cudaGetSymbolAddress((void**)&xh,    g_xh);
    cudaGetSymbolAddress((void**)&ench,  g_ench);
    cudaGetSymbolAddress((void**)&h0f,   g_h0f);
    cudaGetSymbolAddress((void**)&h0h,   g_h0h);
    cudaGetSymbolAddress((void**)&gates, g_gates);
    cudaGetSymbolAddress((void**)&h1h,   g_h1h);
    cudaGetSymbolAddress((void**)&wh,    g_wh);
    cudaGetSymbolAddress((void**)&bwh,   g_bwh);
    cudaGetSymbolAddress((void**)&b1,    g_b1);
    cudaGetSymbolAddress((void**)&b2,    g_b2);

    __half* w_ih1h = wh;                                  // 8M halves
    __half* w_ih2h = wh + (size_t)8  * 1024 * 1024;       // 4M
    __half* w_hh1f = wh + (size_t)12 * 1024 * 1024;       // 2M (folded)
    __half* w_hh2f = wh + (size_t)14 * 1024 * 1024;       // 2M (folded)

    cudaFuncSetAttribute(gemm_fp16_kernel,
                         cudaFuncAttributeMaxDynamicSharedMemorySize, SMEM_BYTES);

    const size_t BLH = (size_t)B_ * LH_;

    // 1) all conversions + w_hh folds + bias sums, one kernel
    prep_all<<<5250, 256>>>((const float4*)w_ih1, (const float4*)w_hh1,
                            (const float4*)w_ih2, (const float4*)w_hh2,
                            (const float4*)bridge_W, (const float4*)enc,
                            (uint2*)w_ih1h, (uint2*)w_ih2h,
                            (uint2*)w_hh1f, (uint2*)w_hh2f,
                            (uint2*)bwh, (uint2*)ench,
                            b_ih1, b_hh1, b1, b_ih2, b_hh2, b2);

    // 2) x = fp16(emb[input])
    gather_kernel<<<(B_ * (E_ / 4)) / 256, 256>>>(input, (const float4*)emb, (uint2*)xh);

    // 3) bridge: h0 = enc @ bridge_W^T + b   (M=B, N=512, K=1024)
    gemm_fp16_kernel<<<dim3(H_ / BN, B_ / BM), 128, SMEM_BYTES>>>(
        ench, bwh, 2 * H_, ench, bwh, 0,
        bridge_b, h0f, h0h, H_, 1);

    // 4) gates1 = x @ w_ih1^T + h0 @ w_hh1f^T + b1   (K = 2048 + 512)
    gemm_fp16_kernel<<<dim3(NG_ / BN, B_ / BM), 128, SMEM_BYTES>>>(
        xh, w_ih1h, E_, h0h, w_hh1f, H_,
        b1, gates, nullptr, NG_, 0);

    // 5) h1: fp16 for GEMM, fp32 into hidden_state[0]
    lstm_act_kernel<<<(B_ * LH_ / 4) / 256, 256>>>(
        (const float4*)gates, (const float4*)h0f,
        (float4*)(out + BLH), nullptr, (__half2*)h1h);

    // 6) gates2 = h1 @ w_ih2^T + h0 @ w_hh2f^T + b2   (K = 1024 + 512)
    gemm_fp16_kernel<<<dim3(NG_ / BN, B_ / BM), 128, SMEM_BYTES>>>(
        h1h, w_ih2h, LH_, h0h, w_hh2f, H_,
        b2, gates, nullptr, NG_, 0);

    // 7) h2 -> output and hidden_state[1]
    lstm_act_kernel<<<(B_ * LH_ / 4) / 256, 256>>>(
        (const float4*)gates, (const float4*)h0f,
        (float4*)out, (float4*)(out + 2 * BLH), nullptr);
}

// round 17
// speedup vs baseline: 1.5151x; 1.1113x over previous
#include <cuda_runtime.h>
#include <cuda_fp16.h>
#include <stdint.h>
#include <math.h>

// ---------------- problem dims ----------------
#define B_   4096
#define H_   512
#define LH_  1024
#define E_   2048
#define NG_  4096   // 4*LH

// ---------------- GEMM tiling ----------------
#define BM 128
#define BN 128
#define BK 64
#define SROW 72                    // halves per smem row (144 B): conflict-free ldmatrix
#define STAGE_B (128 * SROW * 2)   // bytes per tile stage (A or B) = 18432
#define NSTAGE 3
#define SMEM_BYTES (2 * NSTAGE * STAGE_B)   // 110592 -> 2 CTAs/SM (221184 <= 228KB)

// ---------------- scratch (static device memory) ----------------
__device__ __half g_xh  [(size_t)B_ * E_];     // embedded input, fp16
__device__ __half g_ench[(size_t)B_ * 2 * H_]; // encoder state, fp16
__device__ float  g_h0f [(size_t)B_ * H_];     // bridge output, fp32 (c_prev half)
__device__ __half g_h0h [(size_t)B_ * H_];     // bridge output, fp16 (GEMM operand)
__device__ float  g_gates[(size_t)B_ * NG_];   // gate pre-activations, fp32
__device__ __half g_h1h [(size_t)B_ * LH_];    // layer-1 hidden, fp16
__device__ __half g_wh  [(size_t)20 * 1024 * 1024]; // fp16 weights: ih1(8M) ih2(4M) hh1f(2M) hh2f(2M)
__device__ __half g_bwh [(size_t)H_ * 2 * H_]; // fp16 bridge_W
__device__ float  g_b1[NG_];                   // b_ih1 + b_hh1
__device__ float  g_b2[NG_];                   // b_ih2 + b_hh2

// ---------------- helpers ----------------
__device__ __forceinline__ uint32_t smem_u32(const void* p)
{
    uint32_t a;
    asm("{ .reg .u64 t; cvta.to.shared.u64 t, %1; cvt.u32.u64 %0, t; }" : "=r"(a) : "l"(p));
    return a;
}

__device__ __forceinline__ void cp16(uint32_t sa, const void* g)
{
    asm volatile("cp.async.cg.shared.global [%0], [%1], 16;" :: "r"(sa), "l"(g));
}

__device__ __forceinline__ void ldsm4(uint32_t* r, uint32_t addr)
{
    asm volatile("ldmatrix.sync.aligned.m8n8.x4.shared.b16 {%0,%1,%2,%3}, [%4];"
                 : "=r"(r[0]), "=r"(r[1]), "=r"(r[2]), "=r"(r[3]) : "r"(addr));
}

__device__ __forceinline__ uint2 pack_h4(float4 v)
{
    __half2 lo = __floats2half2_rn(v.x, v.y);
    __half2 hi = __floats2half2_rn(v.z, v.w);
    uint2 o;
    o.x = *(const uint32_t*)&lo;
    o.y = *(const uint32_t*)&hi;
    return o;
}

__device__ __forceinline__ void f2h_block(const float4* __restrict__ src,
                                          uint2* __restrict__ dst, int blk)
{
    int base = blk * 1024 + threadIdx.x;
    float4 v0 = src[base];
    float4 v1 = src[base + 256];
    float4 v2 = src[base + 512];
    float4 v3 = src[base + 768];
    dst[base]       = pack_h4(v0);
    dst[base + 256] = pack_h4(v1);
    dst[base + 512] = pack_h4(v2);
    dst[base + 768] = pack_h4(v3);
}

// fold a [NG, 1024] w_hh into [NG, 512] fp16: out[n,k] = w[n,k] + w[n,k+512]
__device__ __forceinline__ void fold_block(const float4* __restrict__ src,
                                           uint2* __restrict__ dst, int blk)
{
    #pragma unroll
    for (int j = 0; j < 4; ++j) {
        int i = blk * 1024 + threadIdx.x + j * 256;  // output float4 index, 128 per row
        int row = i >> 7;
        int c4  = i & 127;
        float4 a = src[row * 256 + c4];
        float4 b = src[row * 256 + c4 + 128];
        float4 s;
        s.x = a.x + b.x; s.y = a.y + b.y; s.z = a.z + b.z; s.w = a.w + b.w;
        dst[i] = pack_h4(s);
    }
}

// ---------------- single merged prep kernel ----------------
// blocks: [0,2048) w_ih1 | [2048,3072) w_ih2 | [3072,3584) fold w_hh1 |
// [3584,4096) fold w_hh2 | [4096,4224) bridge_W | [4224,5248) enc | 5248 b1 | 5249 b2
__global__ void prep_all(const float4* __restrict__ w_ih1, const float4* __restrict__ w_hh1,
                         const float4* __restrict__ w_ih2, const float4* __restrict__ w_hh2,
                         const float4* __restrict__ bw,    const float4* __restrict__ enc,
                         uint2* __restrict__ w_ih1h, uint2* __restrict__ w_ih2h,
                         uint2* __restrict__ w_hh1f, uint2* __restrict__ w_hh2f,
                         uint2* __restrict__ bwh,    uint2* __restrict__ ench,
                         const float* __restrict__ bi1a, const float* __restrict__ bi1b,
                         float* __restrict__ b1,
                         const float* __restrict__ bi2a, const float* __restrict__ bi2b,
                         float* __restrict__ b2)
{
    int b = blockIdx.x;
    if (b < 2048)       f2h_block(w_ih1, w_ih1h, b);
    else if (b < 3072)  f2h_block(w_ih2, w_ih2h, b - 2048);
    else if (b < 3584)  fold_block(w_hh1, w_hh1f, b - 3072);
    else if (b < 4096)  fold_block(w_hh2, w_hh2f, b - 3584);
    else if (b < 4224)  f2h_block(bw,    bwh,    b - 4096);
    else if (b < 5248)  f2h_block(enc,   ench,   b - 4224);
    else if (b == 5248) {
        for (int i = threadIdx.x; i < NG_; i += 256) b1[i] = bi1a[i] + bi1b[i];
    } else {
        for (int i = threadIdx.x; i < NG_; i += 256) b2[i] = bi2a[i] + bi2b[i];
    }
}

__global__ void gather_kernel(const int* __restrict__ input,
                              const float4* __restrict__ emb,
                              uint2* __restrict__ xh)
{
    int idx = blockIdx.x * blockDim.x + threadIdx.x;   // over B * (E/4)
    int b = idx >> 9;            // E/4 = 512
    int j = idx & 511;
    int tok = input[b];
    xh[idx] = pack_h4(emb[(size_t)tok * 512 + j]);
}

// ---------------- fp16 mma.sync GEMM (BK=64, one barrier per 64-K tile) ----------------
// 128 threads, 4 warps of 64x64; 3-stage cp.async; ldmatrix per-k16 slice.
// C[M,N] = A1 @ W1^T + A2 @ W2^T + bias   (half operands K-major, fp32 accum)
// K1, K2 multiples of 64.
// epi=0: C[row*N + col] = v  (gates)
// epi=1: bridge (N=512): C fp32 [B,512] and Ch fp16 [B,512]
__global__ void __launch_bounds__(128, 2)
gemm_fp16_kernel(const __half* __restrict__ A1, const __half* __restrict__ W1, int K1,
                 const __half* __restrict__ A2, const __half* __restrict__ W2, int K2,
                 const float* __restrict__ bias,
                 float* __restrict__ C, __half* __restrict__ Ch, int N, int epi)
{
    extern __shared__ __half smem[];
    const uint32_t sbase = smem_u32(smem);
    const int tid  = threadIdx.x;
    const int lane = tid & 31;
    const int warp = tid >> 5;
    const int wm = (warp & 1) * 64;
    const int wn = (warp >> 1) * 64;
    const int bm = blockIdx.y * BM;
    const int bn = blockIdx.x * BN;

    float acc[4][8][4];
    #pragma unroll
    for (int mi = 0; mi < 4; ++mi)
        #pragma unroll
        for (int ni = 0; ni < 8; ++ni)
            #pragma unroll
            for (int r = 0; r < 4; ++r)
                acc[mi][ni][r] = 0.0f;

    const int nk = (K1 + K2) / BK;

    auto load_tile = [&](int kt, int s) {
        int kk = kt * BK;
        const __half* As; const __half* Bs; int ld;
        if (kk < K1) { As = A1 + kk; Bs = W1 + kk; ld = K1; }
        else         { As = A2 + (kk - K1); Bs = W2 + (kk - K1); ld = K2; }
        uint32_t a_dst = sbase + s * STAGE_B;
        uint32_t b_dst = sbase + NSTAGE * STAGE_B + s * STAGE_B;
        #pragma unroll
        for (int it = 0; it < 8; ++it) {
            int idx = tid + it * 128;       // 0..1023
            int row = idx >> 3;             // 0..127
            int c8  = (idx & 7) << 3;       // half offset 0..56
            cp16(a_dst + (row * SROW + c8) * 2, As + (size_t)(bm + row) * ld + c8);
            cp16(b_dst + (row * SROW + c8) * 2, Bs + (size_t)(bn + row) * ld + c8);
        }
        asm volatile("cp.async.commit_group;");
    };

    load_tile(0, 0);
    load_tile(1, 1);

    // per-lane ldmatrix base addresses (bytes)
    const uint32_t base_a = sbase +
        (((wm + (lane & 15)) * SROW + ((lane >> 4) << 3)) << 1);
    const uint32_t base_b = sbase + NSTAGE * STAGE_B +
        (((wn + (lane & 7) + ((lane >> 4) << 3)) * SROW + (((lane >> 3) & 1) << 3)) << 1);

    for (int kt = 0; kt < nk; ++kt) {
        if (kt + 1 < nk) asm volatile("cp.async.wait_group 1;");
        else             asm volatile("cp.async.wait_group 0;");
        __syncthreads();
        if (kt + 2 < nk) load_tile(kt + 2, (kt + 2) % NSTAGE);

        const int s = kt % NSTAGE;
        const uint32_t sa = base_a + s * STAGE_B;
        const uint32_t sb = base_b + s * STAGE_B;

        #pragma unroll
        for (int ks = 0; ks < 4; ++ks) {            // four k16 slices of BK=64
            uint32_t a[4][4], b[4][4];
            #pragma unroll
            for (int mi = 0; mi < 4; ++mi)
                ldsm4(a[mi], sa + ((mi * 16 * SROW + ks * 16) << 1));
            #pragma unroll
            for (int g = 0; g < 4; ++g)
                ldsm4(b[g], sb + ((g * 16 * SROW + ks * 16) << 1));
            #pragma unroll
            for (int mi = 0; mi < 4; ++mi)
                #pragma unroll
                for (int ni = 0; ni < 8; ++ni) {
                    float* d = acc[mi][ni];
                    uint32_t b0 = b[ni >> 1][(ni & 1) * 2];
                    uint32_t b1 = b[ni >> 1][(ni & 1) * 2 + 1];
                    asm volatile(
                        "mma.sync.aligned.m16n8k16.row.col.f32.f16.f16.f32 "
                        "{%0,%1,%2,%3}, {%4,%5,%6,%7}, {%8,%9}, {%0,%1,%2,%3};"
                        : "+f"(d[0]), "+f"(d[1]), "+f"(d[2]), "+f"(d[3])
                        : "r"(a[mi][0]), "r"(a[mi][1]), "r"(a[mi][2]), "r"(a[mi][3]),
                          "r"(b0), "r"(b1));
                }
        }
    }

    // epilogue
    #pragma unroll
    for (int mi = 0; mi < 4; ++mi) {
        int r0 = bm + wm + mi * 16 + (lane >> 2);
        #pragma unroll
        for (int ni = 0; ni < 8; ++ni) {
            int c0 = bn + wn + ni * 8 + ((lane & 3) << 1);
            float bv0 = bias[c0], bv1 = bias[c0 + 1];
            float v00 = acc[mi][ni][0] + bv0;
            float v01 = acc[mi][ni][1] + bv1;
            float v10 = acc[mi][ni][2] + bv0;
            float v11 = acc[mi][ni][3] + bv1;
            if (epi == 0) {
                *(float2*)(C + (size_t)r0 * N + c0)       = make_float2(v00, v01);
                *(float2*)(C + (size_t)(r0 + 8) * N + c0) = make_float2(v10, v11);
            } else {
                size_t o0 = (size_t)r0 * H_ + c0;
                size_t o1 = (size_t)(r0 + 8) * H_ + c0;
                *(float2*)(C + o0)   = make_float2(v00, v01);
                *(float2*)(C + o1)   = make_float2(v10, v11);
                *(__half2*)(Ch + o0) = __floats2half2_rn(v00, v01);
                *(__half2*)(Ch + o1) = __floats2half2_rn(v10, v11);
            }
        }
    }
}

// ---------------- LSTM pointwise activation (float4) ----------------
// gates [B, 4LH] blocks i,f,g,o; cprev = h0f [B, 512] fp32 (c_prev = dup(h0)).
__global__ void lstm_act_kernel(const float4* __restrict__ gates,
                                const float4* __restrict__ cprev,
                                float4* __restrict__ outF1,
                                float4* __restrict__ outF2,
                                __half2* __restrict__ outH)
{
    int idx = blockIdx.x * blockDim.x + threadIdx.x;   // over B*LH/4
    int b  = idx >> 8;           // LH/4 = 256
    int n4 = idx & 255;
    const float4* g = gates + (size_t)b * 1024 + n4;   // row = 1024 float4
    float4 gi = g[0];
    float4 gf = g[256];
    float4 gg = g[512];
    float4 go = g[768];
    float4 cp = cprev[b * 128 + (n4 & 127)];           // dup(h0): index mod 512
    float4 h;
    {
        float i0 = 1.0f / (1.0f + expf(-gi.x));
        float f0 = 1.0f / (1.0f + expf(-gf.x));
        float o0 = 1.0f / (1.0f + expf(-go.x));
        float c0 = f0 * cp.x + i0 * tanhf(gg.x);
        h.x = o0 * tanhf(c0);
        float i1 = 1.0f / (1.0f + expf(-gi.y));
        float f1 = 1.0f / (1.0f + expf(-gf.y));
        float o1 = 1.0f / (1.0f + expf(-go.y));
        float c1 = f1 * cp.y + i1 * tanhf(gg.y);
        h.y = o1 * tanhf(c1);
        float i2 = 1.0f / (1.0f + expf(-gi.z));
        float f2 = 1.0f / (1.0f + expf(-gf.z));
        float o2 = 1.0f / (1.0f + expf(-go.z));
        float c2 = f2 * cp.z + i2 * tanhf(gg.z);
        h.z = o2 * tanhf(c2);
        float i3 = 1.0f / (1.0f + expf(-gi.w));
        float f3 = 1.0f / (1.0f + expf(-gf.w));
        float o3 = 1.0f / (1.0f + expf(-go.w));
        float c3 = f3 * cp.w + i3 * tanhf(gg.w);
        h.w = o3 * tanhf(c3);
    }
    outF1[idx] = h;
    if (outF2) outF2[idx] = h;
    if (outH) {
        outH[idx * 2]     = __floats2half2_rn(h.x, h.y);
        outH[idx * 2 + 1] = __floats2half2_rn(h.z, h.w);
    }
}

// ---------------- launch ----------------
extern "C" void kernel_launch(void* const* d_in, const int* in_sizes, int n_in,
                              void* d_out, int out_size)
{
    const int*   input    = (const int*)d_in[0];
    const float* enc      = (const float*)d_in[1];
    const float* bridge_W = (const float*)d_in[2];
    const float* bridge_b = (const float*)d_in[3];
    const float* emb      = (const float*)d_in[4];
    const float* w_ih1    = (const float*)d_in[5];
    const float* w_hh1    = (const float*)d_in[6];
    const float* b_ih1    = (const float*)d_in[7];
    const float* b_hh1    = (const float*)d_in[8];
    const float* w_ih2    = (const float*)d_in[9];
    const float* w_hh2    = (const float*)d_in[10];
    const float* b_ih2    = (const float*)d_in[11];
    const float* b_hh2    = (const float*)d_in[12];
    float* out = (float*)d_out;

    __half *xh, *ench, *h0h, *h1h, *wh, *bwh;
    float *h0f, *gates, *b1, *b2;
    cudaGetSymbolAddress((void**)&xh,    g_xh);
    cudaGetSymbolAddress((void**)&ench,  g_ench);
    cudaGetSymbolAddress((void**)&h0f,   g_h0f);
    cudaGetSymbolAddress((void**)&h0h,   g_h0h);
    cudaGetSymbolAddress((void**)&gates, g_gates);
    cudaGetSymbolAddress((void**)&h1h,   g_h1h);
    cudaGetSymbolAddress((void**)&wh,    g_wh);
    cudaGetSymbolAddress((void**)&bwh,   g_bwh);
    cudaGetSymbolAddress((void**)&b1,    g_b1);
    cudaGetSymbolAddress((void**)&b2,    g_b2);

    __half* w_ih1h = wh;                                  // 8M halves
    __half* w_ih2h = wh + (size_t)8  * 1024 * 1024;       // 4M
    __half* w_hh1f = wh + (size_t)12 * 1024 * 1024;       // 2M (folded)
    __half* w_hh2f = wh + (size_t)14 * 1024 * 1024;       // 2M (folded)

    cudaFuncSetAttribute(gemm_fp16_kernel,
                         cudaFuncAttributeMaxDynamicSharedMemorySize, SMEM_BYTES);

    const size_t BLH = (size_t)B_ * LH_;

    // 1) all conversions + w_hh folds + bias sums, one kernel
    prep_all<<<5250, 256>>>((const float4*)w_ih1, (const float4*)w_hh1,
                            (const float4*)w_ih2, (const float4*)w_hh2,
                            (const float4*)bridge_W, (const float4*)enc,
                            (uint2*)w_ih1h, (uint2*)w_ih2h,
                            (uint2*)w_hh1f, (uint2*)w_hh2f,
                            (uint2*)bwh, (uint2*)ench,
                            b_ih1, b_hh1, b1, b_ih2, b_hh2, b2);

    // 2) x = fp16(emb[input])
    gather_kernel<<<(B_ * (E_ / 4)) / 256, 256>>>(input, (const float4*)emb, (uint2*)xh);

    // 3) bridge: h0 = enc @ bridge_W^T + b   (M=B, N=512, K=1024)
    gemm_fp16_kernel<<<dim3(H_ / BN, B_ / BM), 128, SMEM_BYTES>>>(
        ench, bwh, 2 * H_, ench, bwh, 0,
        bridge_b, h0f, h0h, H_, 1);

    // 4) gates1 = x @ w_ih1^T + h0 @ w_hh1f^T + b1   (K = 2048 + 512)
    gemm_fp16_kernel<<<dim3(NG_ / BN, B_ / BM), 128, SMEM_BYTES>>>(
        xh, w_ih1h, E_, h0h, w_hh1f, H_,
        b1, gates, nullptr, NG_, 0);

    // 5) h1: fp16 for GEMM, fp32 into hidden_state[0]
    lstm_act_kernel<<<(B_ * LH_ / 4) / 256, 256>>>(
        (const float4*)gates, (const float4*)h0f,
        (float4*)(out + BLH), nullptr, (__half2*)h1h);

    // 6) gates2 = h1 @ w_ih2^T + h0 @ w_hh2f^T + b2   (K = 1024 + 512)
    gemm_fp16_kernel<<<dim3(NG_ / BN, B_ / BM), 128, SMEM_BYTES>>>(
        h1h, w_ih2h, LH_, h0h, w_hh2f, H_,
        b2, gates, nullptr, NG_, 0);

    // 7) h2 -> output and hidden_state[1]
    lstm_act_kernel<<<(B_ * LH_ / 4) / 256, 256>>>(
        (const float4*)gates, (const float4*)h0f,
        (float4*)out, (float4*)(out + 2 * BLH), nullptr);
}